// round 10
// baseline (speedup 1.0000x reference)
#include <cuda_runtime.h>
#include <cuda_bf16.h>

// GaussianRender, fully fused single kernel: 512 CTAs = 64 tiles x 8 bands
// (8 rows each), 128 threads. alpha = clip(op*prob, .01, .99): gaussians
// provably far from the band (Schur bound per axis) contribute exactly
// alpha=0.01 to every band pixel; runs of far gaussians collapse to the
// closed form  acc += q*T0*S1 - q^2*S2rel, T -= q*m  (pixel-independent).
// Each CTA: gather tile gaussians -> band near/far ballot -> warp-per-entry
// gap reduction -> branch-free packed-f32x2 render, all in one launch.

#define KG     256
#define WIMG   512
#define EU     16            // u64 per entry (128 B)
#define EMAXB  (KG + 1)      // worst-case entries per band

typedef unsigned long long u64;
union F2U { float2 f; u64 u; };

__device__ __forceinline__ u64 pk(float a, float b) { F2U t; t.f = make_float2(a, b); return t.u; }
__device__ __forceinline__ u64 ffma2(u64 a, u64 b, u64 c) {
    u64 d; asm("fma.rn.f32x2 %0, %1, %2, %3;" : "=l"(d) : "l"(a), "l"(b), "l"(c)); return d;
}
__device__ __forceinline__ u64 fmul2(u64 a, u64 b) {
    u64 d; asm("mul.rn.f32x2 %0, %1, %2;" : "=l"(d) : "l"(a), "l"(b)); return d;
}
__device__ __forceinline__ u64 fadd2(u64 a, u64 b) {
    u64 d; asm("add.rn.f32x2 %0, %1, %2;" : "=l"(d) : "l"(a), "l"(b)); return d;
}
__device__ __forceinline__ float ex2f(float x) {
    float y; asm("ex2.approx.f32 %0, %1;" : "=f"(y) : "f"(x)); return y;
}
__device__ __forceinline__ float lg2f(float x) {
    float y; asm("lg2.approx.f32 %0, %1;" : "=f"(y) : "f"(x)); return y;
}
__device__ __forceinline__ float clampa(float a) { return fminf(fmaxf(a, 0.01f), 0.99f); }

// entry as ulonglong2[8]:
//  v0={s1r,s1g} v1={s1b,s2r} v2={s2g,s2b} v3={scnt,-mx}
//  v4={-my,k1}  v5={k2,k3}   v6={lop,cr}  v7={cg,cb}
#define ENT_BODY(P)                                                          \
    {                                                                        \
        const ulonglong2 v0 = (P)[0], v1 = (P)[1], v2 = (P)[2], v3 = (P)[3]; \
        const ulonglong2 v4 = (P)[4], v5 = (P)[5], v6 = (P)[6], v7 = (P)[7]; \
        aR0 = ffma2(trA, v0.x, aR0);  aR0 = fadd2(aR0, v1.y);                \
        aG0 = ffma2(trA, v0.y, aG0);  aG0 = fadd2(aG0, v2.x);                \
        aB0 = ffma2(trA, v1.x, aB0);  aB0 = fadd2(aB0, v2.y);                \
        trA = fadd2(trA, v3.x);                                              \
        aR1 = ffma2(trB, v0.x, aR1);  aR1 = fadd2(aR1, v1.y);                \
        aG1 = ffma2(trB, v0.y, aG1);  aG1 = fadd2(aG1, v2.x);                \
        aB1 = ffma2(trB, v1.x, aB1);  aB1 = fadd2(aB1, v2.y);                \
        trB = fadd2(trB, v3.x);                                              \
        const u64 dx2 = fadd2(px2, v3.y);                                    \
        const u64 t0  = fmul2(v4.y, dx2);                                    \
        const u64 u2  = ffma2(t0, dx2, v6.x);                                \
        const u64 kx2 = fmul2(v5.x, dx2);                                    \
        const u64 dyA = fadd2(pyA, v4.x);                                    \
        const u64 qA  = ffma2(v5.y, dyA, kx2);                               \
        const u64 pwA = ffma2(dyA, qA, u2);                                  \
        const u64 dyB = fadd2(pyB, v4.x);                                    \
        const u64 qB  = ffma2(v5.y, dyB, kx2);                               \
        const u64 pwB = ffma2(dyB, qB, u2);                                  \
        F2U PA, PB; PA.u = pwA; PB.u = pwB;                                  \
        F2U alA, alB;                                                        \
        alA.f.x = clampa(ex2f(PA.f.x));                                      \
        alA.f.y = clampa(ex2f(PA.f.y));                                      \
        alB.f.x = clampa(ex2f(PB.f.x));                                      \
        alB.f.y = clampa(ex2f(PB.f.y));                                      \
        const u64 wvA = fmul2(alA.u, trA);                                   \
        trA = ffma2(alA.u, m1, trA);                                         \
        const u64 wvB = fmul2(alB.u, trB);                                   \
        trB = ffma2(alB.u, m1, trB);                                         \
        aR0 = ffma2(wvA, v6.y, aR0);                                         \
        aG0 = ffma2(wvA, v7.x, aG0);                                         \
        aB0 = ffma2(wvA, v7.y, aB0);                                         \
        aR1 = ffma2(wvB, v6.y, aR1);                                         \
        aG1 = ffma2(wvB, v7.x, aG1);                                         \
        aB1 = ffma2(wvB, v7.y, aB1);                                         \
    }

__global__ __launch_bounds__(128)
void fused_kernel(const float* __restrict__ mu,
                  const float* __restrict__ cov,
                  const float* __restrict__ opac,
                  const float* __restrict__ col,
                  const int*   __restrict__ tidx,
                  float*       __restrict__ out)
{
    // rec: [0]=-mx [1]=-my [2]=k1 [3]=k2 [4]=k3 [5]=lop [6]=cr [7]=cg [8]=cb
    __shared__ float rec[KG][9];                          // 9.2 KB
    __shared__ __align__(16) u64 ent[EMAXB * EU];         // 32.9 KB
    __shared__ unsigned int wmask[8];
    __shared__ int sbase[8];
    __shared__ int snears[KG];
    __shared__ int s_nn;

    const int bid  = blockIdx.x;
    const int t    = bid >> 3;       // tile 0..63
    const int b    = bid & 7;        // band 0..7 (8 rows)
    const int tx   = t & 7;
    const int ty   = t >> 3;
    const int tid  = threadIdx.x;    // 0..127
    const int lane = tid & 31;
    const int warp = tid >> 5;

    const float x0  = (float)(tx * 64) + 0.5f, x1 = x0 + 63.0f;
    const float yb0 = (float)(ty * 64 + b * 8) + 0.5f, yb1 = yb0 + 7.0f;

    // ---- phase 1: gather 2 gaussians/thread, params + band-near ballot ----
    #pragma unroll
    for (int i = 0; i < 2; ++i) {
        const int j = tid + 128 * i;
        const int g = tidx[t * KG + j];
        const float4 cv = *(const float4*)(cov + g * 4);
        const float2 m  = *(const float2*)(mu + g * 2);
        const float det = fmaxf(fmaf(cv.x, cv.w, -cv.y * cv.z), 1e-6f);
        const float inv = 1.0f / det;
        const float e  = -0.7213475204444817f;   // -0.5 * log2(e)
        const float k1 = e * cv.w * inv;
        const float k2 = -e * (cv.y + cv.z) * inv;
        const float k3 = e * cv.x * inv;
        const float lop = lg2f(opac[g]);

        // Schur bound: log2(alpha) <= lop + min(e*mdx^2/cov_xx, e*mdy^2/cov_yy)
        const float dlo = x0 - m.x, dhi = x1 - m.x;
        const float mdx = fmaxf(fmaxf(dlo, -dhi), 0.0f);
        const float elo = yb0 - m.y, ehi = yb1 - m.y;
        const float mdy = fmaxf(fmaxf(elo, -ehi), 0.0f);
        const float bx = __fdividef(e * mdx * mdx, cv.x);
        const float by = __fdividef(e * mdy * mdy, cv.w);
        const bool isNear = !(fminf(bx, by) + lop < (-6.6438561897747395f - 0.01f));

        rec[j][0] = -m.x;  rec[j][1] = -m.y;
        rec[j][2] = k1;    rec[j][3] = k2;
        rec[j][4] = k3;    rec[j][5] = lop;
        rec[j][6] = col[g * 3 + 0];
        rec[j][7] = col[g * 3 + 1];
        rec[j][8] = col[g * 3 + 2];

        const unsigned int mask = __ballot_sync(0xffffffffu, isNear);
        if (lane == 0) wmask[i * 4 + warp] = mask;
    }
    __syncthreads();

    // ---- phase 2: scan -> ordered near list ----
    if (tid == 0) {
        int a = 0;
        #pragma unroll
        for (int w = 0; w < 8; ++w) { sbase[w] = a; a += __popc(wmask[w]); }
        s_nn = a;
    }
    __syncthreads();
    #pragma unroll
    for (int i = 0; i < 2; ++i) {
        const int j = tid + 128 * i;
        const unsigned int mask = wmask[i * 4 + warp];
        if (mask & (1u << lane)) {
            const int rank = sbase[i * 4 + warp] + __popc(mask & ((1u << lane) - 1u));
            snears[rank] = j;
        }
    }
    __syncthreads();
    const int nn = s_nn;             // entries = nn + 1

    // ---- phase 3: one warp per entry; gap reduction + entry write ----
    for (int i = warp; i <= nn; i += 4) {
        const int start = (i == 0) ? 0 : snears[i - 1] + 1;
        const int end   = (i < nn) ? snears[i] - 1 : KG - 1;

        float S1r = 0.f, S1g = 0.f, S1b = 0.f;
        float S2r = 0.f, S2g = 0.f, S2b = 0.f;
        for (int j = start + lane; j <= end; j += 32) {
            const float rel = (float)(j - start);
            const float cr = rec[j][6], cg = rec[j][7], cb = rec[j][8];
            S1r += cr; S1g += cg; S1b += cb;
            S2r = fmaf(rel, cr, S2r);
            S2g = fmaf(rel, cg, S2g);
            S2b = fmaf(rel, cb, S2b);
        }
        #pragma unroll
        for (int o = 16; o >= 1; o >>= 1) {
            S1r += __shfl_xor_sync(0xffffffffu, S1r, o);
            S1g += __shfl_xor_sync(0xffffffffu, S1g, o);
            S1b += __shfl_xor_sync(0xffffffffu, S1b, o);
            S2r += __shfl_xor_sync(0xffffffffu, S2r, o);
            S2g += __shfl_xor_sync(0xffffffffu, S2g, o);
            S2b += __shfl_xor_sync(0xffffffffu, S2b, o);
        }
        if (lane == 0) {
            const float q = 0.01f;
            const float cm = (float)(end - start + 1);   // may be 0 (empty gap)
            u64* p = ent + i * EU;
            p[0] = pk(q * S1r, q * S1r);
            p[1] = pk(q * S1g, q * S1g);
            p[2] = pk(q * S1b, q * S1b);
            p[3] = pk(-q * q * S2r, -q * q * S2r);
            p[4] = pk(-q * q * S2g, -q * q * S2g);
            p[5] = pk(-q * q * S2b, -q * q * S2b);
            p[6] = pk(-q * cm, -q * cm);
            if (i < nn) {
                const int j = snears[i];
                #pragma unroll
                for (int r = 0; r < 9; ++r) { const float v = rec[j][r]; p[7 + r] = pk(v, v); }
            } else {
                // dummy near: zero k/lop/mu/colors -> acc unchanged; tr
                // corrupted only after its last use.
                #pragma unroll
                for (int r = 7; r < 16; ++r) p[r] = 0ull;
            }
        }
    }
    __syncthreads();

    // ---- phase 4: branch-free render, 4 px/thread ----
    const int lx = tid & 63;
    const int h  = tid >> 6;
    const float px  = (float)(tx * 64 + lx) + 0.5f;
    const float py0 = yb0 + (float)(h * 4);
    const u64 px2 = pk(px, px);
    const u64 pyA = pk(py0, py0 + 1.0f);
    const u64 pyB = pk(py0 + 2.0f, py0 + 3.0f);
    const u64 m1  = pk(-1.0f, -1.0f);

    u64 aR0 = 0, aG0 = 0, aB0 = 0, aR1 = 0, aG1 = 0, aB1 = 0;
    u64 trA = pk(1.0f, 1.0f), trB = pk(1.0f, 1.0f);

    const int cnt = nn + 1;
    const ulonglong2* p = (const ulonglong2*)ent;
    #pragma unroll 2
    for (int e = 0; e < cnt; ++e, p += 8) ENT_BODY(p)

    // ---- epilogue: write 4 pixels ----
    const int gx = tx * 64 + lx;
    const int gy = ty * 64 + b * 8 + h * 4;
    F2U R0, G0, B0, R1, G1, B1;
    R0.u = aR0; G0.u = aG0; B0.u = aB0;
    R1.u = aR1; G1.u = aG1; B1.u = aB1;
    float* o = out + ((size_t)gy * WIMG + gx) * 3;
    o[0] = R0.f.x; o[1] = G0.f.x; o[2] = B0.f.x;  o += WIMG * 3;
    o[0] = R0.f.y; o[1] = G0.f.y; o[2] = B0.f.y;  o += WIMG * 3;
    o[0] = R1.f.x; o[1] = G1.f.x; o[2] = B1.f.x;  o += WIMG * 3;
    o[0] = R1.f.y; o[1] = G1.f.y; o[2] = B1.f.y;
}

extern "C" void kernel_launch(void* const* d_in, const int* in_sizes, int n_in,
                              void* d_out, int out_size)
{
    const float* mu   = (const float*)d_in[0];
    const float* cov  = (const float*)d_in[1];
    const float* opac = (const float*)d_in[2];
    const float* col  = (const float*)d_in[3];
    const int*   tidx = (const int*)  d_in[4];
    float* out = (float*)d_out;

    // 64 tiles x 8 bands = 512 CTAs, 128 threads, single fused launch
    fused_kernel<<<512, 128>>>(mu, cov, opac, col, tidx, out);
}

// round 11
// speedup vs baseline: 1.0226x; 1.0226x over previous
#include <cuda_runtime.h>
#include <cuda_bf16.h>

// GaussianRender, fused single kernel: 1024 CTAs = 64 tiles x 16 bands
// (4 rows each), 128 threads, 2 px/thread. alpha = clip(op*prob,.01,.99):
// gaussians provably far from the band (per-axis Schur bound) contribute
// exactly alpha=0.01 to every band pixel; runs of far gaussians collapse to
//   acc += q*T0*S1 - q^2*S2rel,  T -= q*m   (pixel-independent sums).
// Per CTA: gather -> band near ballot -> warp-per-entry gap reduction ->
// branch-free packed-f32x2 render. Entry cap 128 with exact brute-force
// fallback (never taken on this input).

#define KG     256
#define WIMG   512
#define EU     16            // u64 per entry (128 B)
#define ECAP   128           // smem entry cap

typedef unsigned long long u64;
union F2U { float2 f; u64 u; };

__device__ __forceinline__ u64 pk(float a, float b) { F2U t; t.f = make_float2(a, b); return t.u; }
__device__ __forceinline__ u64 ffma2(u64 a, u64 b, u64 c) {
    u64 d; asm("fma.rn.f32x2 %0, %1, %2, %3;" : "=l"(d) : "l"(a), "l"(b), "l"(c)); return d;
}
__device__ __forceinline__ u64 fmul2(u64 a, u64 b) {
    u64 d; asm("mul.rn.f32x2 %0, %1, %2;" : "=l"(d) : "l"(a), "l"(b)); return d;
}
__device__ __forceinline__ u64 fadd2(u64 a, u64 b) {
    u64 d; asm("add.rn.f32x2 %0, %1, %2;" : "=l"(d) : "l"(a), "l"(b)); return d;
}
__device__ __forceinline__ float ex2f(float x) {
    float y; asm("ex2.approx.f32 %0, %1;" : "=f"(y) : "f"(x)); return y;
}
__device__ __forceinline__ float lg2f(float x) {
    float y; asm("lg2.approx.f32 %0, %1;" : "=f"(y) : "f"(x)); return y;
}
__device__ __forceinline__ float clampa(float a) { return fminf(fmaxf(a, 0.01f), 0.99f); }

__global__ __launch_bounds__(128)
void fused_kernel(const float* __restrict__ mu,
                  const float* __restrict__ cov,
                  const float* __restrict__ opac,
                  const float* __restrict__ col,
                  const int*   __restrict__ tidx,
                  float*       __restrict__ out)
{
    // rec: [0]=-mx [1]=-my [2]=k1 [3]=k2 [4]=k3 [5]=lop [6]=cr [7]=cg [8]=cb
    __shared__ float rec[KG][9];                          // 9.2 KB
    __shared__ __align__(16) u64 ent[ECAP * EU];          // 16 KB
    __shared__ unsigned int wmask[8];
    __shared__ int sbase[8];
    __shared__ int snears[KG];
    __shared__ int s_nn;

    const int bid  = blockIdx.x;
    const int t    = bid >> 4;       // tile 0..63
    const int b    = bid & 15;       // band 0..15 (4 rows)
    const int tx   = t & 7;
    const int ty   = t >> 3;
    const int tid  = threadIdx.x;    // 0..127
    const int lane = tid & 31;
    const int warp = tid >> 5;

    const float x0  = (float)(tx * 64) + 0.5f, x1 = x0 + 63.0f;
    const float yb0 = (float)(ty * 64 + b * 4) + 0.5f, yb1 = yb0 + 3.0f;

    // ---- phase 1: gather 2 gaussians/thread, params + band-near ballot ----
    #pragma unroll
    for (int i = 0; i < 2; ++i) {
        const int j = tid + 128 * i;
        const int g = __ldg(tidx + t * KG + j);
        const float4 cv = __ldg((const float4*)(cov + g * 4));
        const float2 m  = __ldg((const float2*)(mu + g * 2));
        const float op  = __ldg(opac + g);
        const float c0  = __ldg(col + g * 3 + 0);
        const float c1  = __ldg(col + g * 3 + 1);
        const float c2  = __ldg(col + g * 3 + 2);

        const float det = fmaxf(fmaf(cv.x, cv.w, -cv.y * cv.z), 1e-6f);
        const float inv = 1.0f / det;
        const float e  = -0.7213475204444817f;   // -0.5 * log2(e)
        const float k1 = e * cv.w * inv;
        const float k2 = -e * (cv.y + cv.z) * inv;
        const float k3 = e * cv.x * inv;
        const float lop = lg2f(op);

        // Schur bound: log2(alpha) <= lop + min(e*mdx^2/cov_xx, e*mdy^2/cov_yy)
        const float dlo = x0 - m.x, dhi = x1 - m.x;
        const float mdx = fmaxf(fmaxf(dlo, -dhi), 0.0f);
        const float elo = yb0 - m.y, ehi = yb1 - m.y;
        const float mdy = fmaxf(fmaxf(elo, -ehi), 0.0f);
        const float bx = __fdividef(e * mdx * mdx, cv.x);
        const float by = __fdividef(e * mdy * mdy, cv.w);
        const bool isNear = !(fminf(bx, by) + lop < (-6.6438561897747395f - 0.01f));

        rec[j][0] = -m.x;  rec[j][1] = -m.y;
        rec[j][2] = k1;    rec[j][3] = k2;
        rec[j][4] = k3;    rec[j][5] = lop;
        rec[j][6] = c0;    rec[j][7] = c1;    rec[j][8] = c2;

        const unsigned int mask = __ballot_sync(0xffffffffu, isNear);
        if (lane == 0) wmask[i * 4 + warp] = mask;
    }
    __syncthreads();

    // ---- phase 2: scan -> ordered near list ----
    if (tid == 0) {
        int a = 0;
        #pragma unroll
        for (int w = 0; w < 8; ++w) { sbase[w] = a; a += __popc(wmask[w]); }
        s_nn = a;
    }
    __syncthreads();
    #pragma unroll
    for (int i = 0; i < 2; ++i) {
        const int j = tid + 128 * i;
        const unsigned int mask = wmask[i * 4 + warp];
        if (mask & (1u << lane)) {
            const int rank = sbase[i * 4 + warp] + __popc(mask & ((1u << lane) - 1u));
            snears[rank] = j;
        }
    }
    __syncthreads();
    const int nn = s_nn;             // entries = nn + 1

    // pixel setup (shared by both paths)
    const int lx = tid & 63;
    const int h  = tid >> 6;
    const float px = (float)(tx * 64 + lx) + 0.5f;
    const float py = yb0 + (float)(h * 2);
    const u64 px2 = pk(px, px);
    const u64 py2 = pk(py, py + 1.0f);
    const u64 m1  = pk(-1.0f, -1.0f);

    u64 aR = 0, aG = 0, aB = 0;
    u64 tr = pk(1.0f, 1.0f);

    if (nn + 1 <= ECAP) {
        // ---- phase 3: one warp per entry; gap reduction + entry write ----
        for (int i = warp; i <= nn; i += 4) {
            const int start = (i == 0) ? 0 : snears[i - 1] + 1;
            const int end   = (i < nn) ? snears[i] - 1 : KG - 1;

            float S1r = 0.f, S1g = 0.f, S1b = 0.f;
            float S2r = 0.f, S2g = 0.f, S2b = 0.f;
            for (int j = start + lane; j <= end; j += 32) {
                const float rel = (float)(j - start);
                const float cr = rec[j][6], cg = rec[j][7], cb = rec[j][8];
                S1r += cr; S1g += cg; S1b += cb;
                S2r = fmaf(rel, cr, S2r);
                S2g = fmaf(rel, cg, S2g);
                S2b = fmaf(rel, cb, S2b);
            }
            #pragma unroll
            for (int o = 16; o >= 1; o >>= 1) {
                S1r += __shfl_xor_sync(0xffffffffu, S1r, o);
                S1g += __shfl_xor_sync(0xffffffffu, S1g, o);
                S1b += __shfl_xor_sync(0xffffffffu, S1b, o);
                S2r += __shfl_xor_sync(0xffffffffu, S2r, o);
                S2g += __shfl_xor_sync(0xffffffffu, S2g, o);
                S2b += __shfl_xor_sync(0xffffffffu, S2b, o);
            }
            if (lane == 0) {
                const float q = 0.01f;
                const float cm = (float)(end - start + 1);
                u64* p = ent + i * EU;
                p[0] = pk(q * S1r, q * S1r);
                p[1] = pk(q * S1g, q * S1g);
                p[2] = pk(q * S1b, q * S1b);
                p[3] = pk(-q * q * S2r, -q * q * S2r);
                p[4] = pk(-q * q * S2g, -q * q * S2g);
                p[5] = pk(-q * q * S2b, -q * q * S2b);
                p[6] = pk(-q * cm, -q * cm);
                if (i < nn) {
                    const int j = snears[i];
                    #pragma unroll
                    for (int r = 0; r < 9; ++r) { const float v = rec[j][r]; p[7 + r] = pk(v, v); }
                } else {
                    #pragma unroll
                    for (int r = 7; r < 16; ++r) p[r] = 0ull;  // dummy near
                }
            }
        }
        __syncthreads();

        // ---- phase 4: branch-free render, 2 px/thread ----
        const int cnt = nn + 1;
        const ulonglong2* p = (const ulonglong2*)ent;
        for (int e = 0; e < cnt; ++e, p += 8) {
            const ulonglong2 v0 = p[0], v1 = p[1], v2 = p[2], v3 = p[3];
            const ulonglong2 v4 = p[4], v5 = p[5], v6 = p[6], v7 = p[7];
            // run prefix
            aR = ffma2(tr, v0.x, aR);  aR = fadd2(aR, v1.y);
            aG = ffma2(tr, v0.y, aG);  aG = fadd2(aG, v2.x);
            aB = ffma2(tr, v1.x, aB);  aB = fadd2(aB, v2.y);
            tr = fadd2(tr, v3.x);
            // near gaussian
            const u64 dx2 = fadd2(px2, v3.y);
            const u64 t0  = fmul2(v4.y, dx2);
            const u64 u2  = ffma2(t0, dx2, v6.x);
            const u64 kx2 = fmul2(v5.x, dx2);
            const u64 dy2 = fadd2(py2, v4.x);
            const u64 q2  = ffma2(v5.y, dy2, kx2);
            const u64 pw  = ffma2(dy2, q2, u2);
            F2U PW; PW.u = pw;
            F2U al;
            al.f.x = clampa(ex2f(PW.f.x));
            al.f.y = clampa(ex2f(PW.f.y));
            const u64 wv = fmul2(al.u, tr);
            tr = ffma2(al.u, m1, tr);
            aR = ffma2(wv, v6.y, aR);
            aG = ffma2(wv, v7.x, aG);
            aB = ffma2(wv, v7.y, aB);
        }
    } else {
        // ---- fallback: exact brute force straight from rec (any input) ----
        __syncthreads();
        for (int k = 0; k < KG; ++k) {
            const float nmx = rec[k][0], nmy = rec[k][1];
            const float k1 = rec[k][2], k2 = rec[k][3], k3 = rec[k][4];
            const float lop = rec[k][5];
            const u64 crr = pk(rec[k][6], rec[k][6]);
            const u64 cgg = pk(rec[k][7], rec[k][7]);
            const u64 cbb = pk(rec[k][8], rec[k][8]);
            const u64 dx2 = fadd2(px2, pk(nmx, nmx));
            const u64 t0  = fmul2(pk(k1, k1), dx2);
            const u64 u2  = ffma2(t0, dx2, pk(lop, lop));
            const u64 kx2 = fmul2(pk(k2, k2), dx2);
            const u64 dy2 = fadd2(py2, pk(nmy, nmy));
            const u64 q2  = ffma2(pk(k3, k3), dy2, kx2);
            const u64 pw  = ffma2(dy2, q2, u2);
            F2U PW; PW.u = pw;
            F2U al;
            al.f.x = clampa(ex2f(PW.f.x));
            al.f.y = clampa(ex2f(PW.f.y));
            const u64 wv = fmul2(al.u, tr);
            tr = ffma2(al.u, m1, tr);
            aR = ffma2(wv, crr, aR);
            aG = ffma2(wv, cgg, aG);
            aB = ffma2(wv, cbb, aB);
        }
    }

    // ---- epilogue: write 2 pixels ----
    const int gx = tx * 64 + lx;
    const int gy = ty * 64 + b * 4 + h * 2;
    F2U R, G, B; R.u = aR; G.u = aG; B.u = aB;
    float* o = out + ((size_t)gy * WIMG + gx) * 3;
    o[0] = R.f.x; o[1] = G.f.x; o[2] = B.f.x;
    o += WIMG * 3;
    o[0] = R.f.y; o[1] = G.f.y; o[2] = B.f.y;
}

extern "C" void kernel_launch(void* const* d_in, const int* in_sizes, int n_in,
                              void* d_out, int out_size)
{
    const float* mu   = (const float*)d_in[0];
    const float* cov  = (const float*)d_in[1];
    const float* opac = (const float*)d_in[2];
    const float* col  = (const float*)d_in[3];
    const int*   tidx = (const int*)  d_in[4];
    float* out = (float*)d_out;

    // 64 tiles x 16 bands = 1024 CTAs, 128 threads, single fused launch
    fused_kernel<<<1024, 128>>>(mu, cov, opac, col, tidx, out);
}